// round 8
// baseline (speedup 1.0000x reference)
#include <cuda_runtime.h>
#include <cuda_bf16.h>
#include <cstdint>
#include <cstddef>

// E=16, D=1024, H=4096, N=16384 (1024 tokens/expert, contiguous).
// GEMM1: per-expert [1024 x 4096 x 1024], relu(X*W1^T + b1) -> hidden (bf16 hi/lo)
// GEMM2: per-expert [1024 x 1024 x 4096], H*W2^T + b2       -> fp32 out
// bf16 hi/lo 3-pass (Ootomo) mma.sync m16n8k16.
// R8: same 128x128x64 tile + 3x64KB cp.async ring as R4/R7, but 512 threads
// (16 warps, 4x4 warp grid, 32x32 warp tile) -> ~110 regs/thread so the full
// 64K RF holds 16 warps/SM (4/SMSP) and LDSM->MMA latency is covered.

static __device__ __nv_bfloat16 g_xs_h[16777216], g_xs_l[16777216];
static __device__ __nv_bfloat16 g_w1_h[67108864], g_w1_l[67108864];
static __device__ __nv_bfloat16 g_w2_h[67108864], g_w2_l[67108864];
static __device__ __nv_bfloat16 g_hid_h[67108864], g_hid_l[67108864];

__device__ __forceinline__ uint32_t smem_u32(const void* p) {
    uint32_t a;
    asm("{ .reg .u64 t; cvta.to.shared.u64 t, %1; cvt.u32.u64 %0, t; }"
        : "=r"(a) : "l"(p));
    return a;
}
#define SW128(x) ((x) ^ (((x) >> 3) & 0x70))

__device__ __forceinline__ uint32_t pack_bf2(float a, float b) {
    uint32_t r;
    asm("cvt.rn.bf16x2.f32 %0, %1, %2;" : "=r"(r) : "f"(b), "f"(a));
    return r;
}
__device__ __forceinline__ void ldsm4(uint32_t* r, uint32_t addr) {
    asm volatile("ldmatrix.sync.aligned.m8n8.x4.shared.b16 {%0,%1,%2,%3}, [%4];"
                 : "=r"(r[0]), "=r"(r[1]), "=r"(r[2]), "=r"(r[3]) : "r"(addr));
}
__device__ __forceinline__ void mma16816(float* c, const uint32_t* a,
                                         uint32_t b0, uint32_t b1) {
    asm volatile(
        "mma.sync.aligned.m16n8k16.row.col.f32.bf16.bf16.f32 "
        "{%0,%1,%2,%3}, {%4,%5,%6,%7}, {%8,%9}, {%0,%1,%2,%3};"
        : "+f"(c[0]), "+f"(c[1]), "+f"(c[2]), "+f"(c[3])
        : "r"(a[0]), "r"(a[1]), "r"(a[2]), "r"(a[3]), "r"(b0), "r"(b1));
}
__device__ __forceinline__ void cp16(uint32_t dst, const void* src) {
    asm volatile("cp.async.cg.shared.global [%0], [%1], 16;"
                 :: "r"(dst), "l"(src) : "memory");
}
#define CP_COMMIT() asm volatile("cp.async.commit_group;" ::: "memory")
#define CP_WAIT1()  asm volatile("cp.async.wait_group 1;" ::: "memory")

// -------- elementwise fp32 -> bf16 hi/lo planes --------
__global__ __launch_bounds__(256)
void split_f32_k(const float4* __restrict__ in, uint2* __restrict__ hi,
                 uint2* __restrict__ lo, int n4) {
    int i = blockIdx.x * 256 + threadIdx.x;
    if (i >= n4) return;
    float4 f = in[i];
    uint32_t h0 = pack_bf2(f.x, f.y), h1 = pack_bf2(f.z, f.w);
    float e0 = __uint_as_float(h0 << 16), e1 = __uint_as_float(h0 & 0xFFFF0000u);
    float e2 = __uint_as_float(h1 << 16), e3 = __uint_as_float(h1 & 0xFFFF0000u);
    hi[i] = make_uint2(h0, h1);
    lo[i] = make_uint2(pack_bf2(f.x - e0, f.y - e1), pack_bf2(f.z - e2, f.w - e3));
}

// SMEM stage (bf16, 64-elem rows = 128B, SW128):
//   Ahi @0 (16KB)  Alo @16384  Bhi @32768  Blo @49152  -> 64KB/stage, 3 stages
static constexpr int STAGE = 65536;
static constexpr int SMEM_TOTAL = 3 * STAGE;  // 192 KB

template <int NCOLS, int KDIM, bool RELU, bool SPLIT>
__global__ __launch_bounds__(512, 1)
void ffn_mma6(const __nv_bfloat16* __restrict__ Ah, const __nv_bfloat16* __restrict__ Al,
              const __nv_bfloat16* __restrict__ Bh, const __nv_bfloat16* __restrict__ Bl,
              const float* __restrict__ bias,
              float* __restrict__ Cf,
              __nv_bfloat16* __restrict__ Ch, __nv_bfloat16* __restrict__ Cl)
{
    constexpr int NK = KDIM / 64;
    extern __shared__ char smem[];
    const uint32_t smb = smem_u32(smem);

    const int tid  = threadIdx.x;
    const int lane = tid & 31, warp = tid >> 5;    // 16 warps
    const int wm = warp >> 2, wn = warp & 3;       // 4x4, warp tile 32(M) x 32(N)
    const int e  = blockIdx.z;
    const int m0 = blockIdx.y * 128, n0 = blockIdx.x * 128;

    const __nv_bfloat16* Abh = Ah + ((size_t)e * 1024 + m0) * KDIM;
    const __nv_bfloat16* Abl = Al + ((size_t)e * 1024 + m0) * KDIM;
    const __nv_bfloat16* Bbh = Bh + ((size_t)e * NCOLS + n0) * KDIM;
    const __nv_bfloat16* Bbl = Bl + ((size_t)e * NCOLS + n0) * KDIM;

    // staging: chunk s = tid + t*512; row = s>>3 (0..127), c = s&7; 8 cp/thread
    int sws[2];
    size_t goff[2];
#pragma unroll
    for (int t = 0; t < 2; t++) {
        int s = tid + (t << 9);
        int row = s >> 3, c = s & 7;
        sws[t]  = SW128(row * 128 + c * 16);
        goff[t] = (size_t)row * KDIM + c * 8;
    }

    // ldmatrix per-thread bases (R4-validated pattern; wm stride now 32 rows)
    const int xmask = (lane & 7) << 4;
    const int a_b0 = (wm * 32 + (lane & 15)) * 128 + ((lane >> 4) & 1) * 16;
    const int b_b0 = (wn * 32 + (lane & 7) + ((lane >> 4) & 1) * 8) * 128 +
                     ((lane >> 3) & 1) * 16;

    float acc[2][4][4];
#pragma unroll
    for (int i = 0; i < 2; i++)
#pragma unroll
        for (int j = 0; j < 4; j++)
#pragma unroll
            for (int q = 0; q < 4; q++) acc[i][j][q] = 0.f;

    auto stage = [&](int kt, uint32_t base) {
        const int kofs = kt * 64;
#pragma unroll
        for (int t = 0; t < 2; t++) {
            const size_t g = goff[t] + kofs;
            cp16(base + sws[t],          Abh + g);
            cp16(base + 16384 + sws[t],  Abl + g);
            cp16(base + 32768 + sws[t],  Bbh + g);
            cp16(base + 49152 + sws[t],  Bbl + g);
        }
    };

    // ---- prologue: fill stages 0,1 ----
    stage(0, smb);         CP_COMMIT();
    stage(1, smb + STAGE); CP_COMMIT();
    CP_WAIT1();            // stage 0 resident
    __syncthreads();

    for (int kt = 0; kt < NK; ++kt) {
        const uint32_t sA = smb + (kt % 3) * STAGE;

        if (kt + 2 < NK) stage(kt + 2, smb + ((kt + 2) % 3) * STAGE);
        CP_COMMIT();  // one group per iter (may be empty at tail)

#pragma unroll
        for (int k16 = 0; k16 < 4; k16++) {
            uint32_t ah[2][4], al[2][4], bh[2][4], bl[2][4];
#pragma unroll
            for (int mt = 0; mt < 2; mt++) {
                int off = (a_b0 + mt * 2048 + k16 * 32) ^ xmask;
                ldsm4(ah[mt], sA + off);
                ldsm4(al[mt], sA + 16384 + off);
            }
#pragma unroll
            for (int nt2 = 0; nt2 < 2; nt2++) {
                int off = (b_b0 + nt2 * 2048 + k16 * 32) ^ xmask;
                ldsm4(bh[nt2], sA + 32768 + off);
                ldsm4(bl[nt2], sA + 49152 + off);
            }
#pragma unroll
            for (int mt = 0; mt < 2; mt++)
#pragma unroll
                for (int nt = 0; nt < 4; nt++) {
                    const int g = nt >> 1, s2 = (nt & 1) * 2;
                    mma16816(acc[mt][nt], ah[mt], bh[g][s2], bh[g][s2 + 1]);
                    mma16816(acc[mt][nt], ah[mt], bl[g][s2], bl[g][s2 + 1]);
                    mma16816(acc[mt][nt], al[mt], bh[g][s2], bh[g][s2 + 1]);
                }
        }

        if (kt + 1 < NK) {
            CP_WAIT1();        // stage kt+1 resident (kt+2 still in flight)
            __syncthreads();   // frees ring slot kt%3
        }
    }

    // ---- epilogue ----
    const float* bp = bias + (size_t)e * NCOLS + n0 + wn * 32;
    float2 bvv[4];
#pragma unroll
    for (int nt = 0; nt < 4; nt++)
        bvv[nt] = *(const float2*)(bp + nt * 8 + (lane & 3) * 2);

    const size_t rbase = (size_t)e * 1024 + m0 + wm * 32;
#pragma unroll
    for (int mt = 0; mt < 2; mt++) {
        int r = mt * 16 + (lane >> 2);
#pragma unroll
        for (int nt = 0; nt < 4; nt++) {
            int col = n0 + wn * 32 + nt * 8 + (lane & 3) * 2;
            float2 v0, v1;
            v0.x = acc[mt][nt][0] + bvv[nt].x;
            v0.y = acc[mt][nt][1] + bvv[nt].y;
            v1.x = acc[mt][nt][2] + bvv[nt].x;
            v1.y = acc[mt][nt][3] + bvv[nt].y;
            if (RELU) {
                v0.x = fmaxf(v0.x, 0.f); v0.y = fmaxf(v0.y, 0.f);
                v1.x = fmaxf(v1.x, 0.f); v1.y = fmaxf(v1.y, 0.f);
            }
            const size_t i0 = (rbase + r) * NCOLS + col;
            const size_t i1 = (rbase + r + 8) * NCOLS + col;
            if (SPLIT) {
                uint32_t h0 = pack_bf2(v0.x, v0.y);
                float e0 = __uint_as_float(h0 << 16), e1 = __uint_as_float(h0 & 0xFFFF0000u);
                uint32_t l0 = pack_bf2(v0.x - e0, v0.y - e1);
                uint32_t h1 = pack_bf2(v1.x, v1.y);
                float e2 = __uint_as_float(h1 << 16), e3 = __uint_as_float(h1 & 0xFFFF0000u);
                uint32_t l1 = pack_bf2(v1.x - e2, v1.y - e3);
                *(uint32_t*)(Ch + i0) = h0;
                *(uint32_t*)(Cl + i0) = l0;
                *(uint32_t*)(Ch + i1) = h1;
                *(uint32_t*)(Cl + i1) = l1;
            } else {
                *(float2*)(Cf + i0) = v0;
                *(float2*)(Cf + i1) = v1;
            }
        }
    }
}

extern "C" void kernel_launch(void* const* d_in, const int* in_sizes, int n_in,
                              void* d_out, int out_size) {
    (void)in_sizes; (void)n_in; (void)out_size;
    const float* xs = (const float*)d_in[0];
    const float* w1 = (const float*)d_in[2];
    const float* b1 = (const float*)d_in[3];
    const float* w2 = (const float*)d_in[4];
    const float* b2 = (const float*)d_in[5];
    float* out = (float*)d_out;

    void *xh, *xl, *w1h, *w1l, *w2h, *w2l, *hh, *hl;
    cudaGetSymbolAddress(&xh,  g_xs_h);  cudaGetSymbolAddress(&xl,  g_xs_l);
    cudaGetSymbolAddress(&w1h, g_w1_h);  cudaGetSymbolAddress(&w1l, g_w1_l);
    cudaGetSymbolAddress(&w2h, g_w2_h);  cudaGetSymbolAddress(&w2l, g_w2_l);
    cudaGetSymbolAddress(&hh,  g_hid_h); cudaGetSymbolAddress(&hl,  g_hid_l);

    cudaFuncSetAttribute(ffn_mma6<4096, 1024, true, true>,
                         cudaFuncAttributeMaxDynamicSharedMemorySize, SMEM_TOTAL);
    cudaFuncSetAttribute(ffn_mma6<1024, 4096, false, false>,
                         cudaFuncAttributeMaxDynamicSharedMemorySize, SMEM_TOTAL);

    // Pre-split operands to bf16 hi/lo planes
    split_f32_k<<<16384, 256>>>((const float4*)xs, (uint2*)xh, (uint2*)xl, 16777216 / 4);
    split_f32_k<<<65536, 256>>>((const float4*)w1, (uint2*)w1h, (uint2*)w1l, 67108864 / 4);
    split_f32_k<<<65536, 256>>>((const float4*)w2, (uint2*)w2h, (uint2*)w2l, 67108864 / 4);

    // GEMM1: bias+relu, split-output hidden planes
    ffn_mma6<4096, 1024, true, true><<<dim3(32, 8, 16), 512, SMEM_TOTAL>>>(
        (const __nv_bfloat16*)xh, (const __nv_bfloat16*)xl,
        (const __nv_bfloat16*)w1h, (const __nv_bfloat16*)w1l,
        b1, nullptr, (__nv_bfloat16*)hh, (__nv_bfloat16*)hl);
    // GEMM2: bias, fp32 out
    ffn_mma6<1024, 4096, false, false><<<dim3(8, 8, 16), 512, SMEM_TOTAL>>>(
        (const __nv_bfloat16*)hh, (const __nv_bfloat16*)hl,
        (const __nv_bfloat16*)w2h, (const __nv_bfloat16*)w2l,
        b2, out, nullptr, nullptr);
}

// round 9
// speedup vs baseline: 1.0007x; 1.0007x over previous
#include <cuda_runtime.h>
#include <cuda_bf16.h>
#include <cstdint>
#include <cstddef>

// E=16, D=1024, H=4096, N=16384 (1024 tokens/expert, contiguous).
// GEMM1: per-expert [1024 x 4096 x 1024], relu(X*W1^T + b1) -> hidden (bf16 hi/lo)
// GEMM2: per-expert [1024 x 1024 x 4096], H*W2^T + b2       -> fp32 out
// bf16 hi/lo 3-pass (Ootomo) mma.sync m16n8k16.
// R9: CTA tile 128x256, 8 warps (2x4), warp tile 64x64. ldsm/MMA ratio drops
// 0.25 -> 0.167 to break the smem-crossbar/tensor co-saturation seen at ~74%.
// 2-stage cp.async ring (96KB/stage = 192KB).

static __device__ __nv_bfloat16 g_xs_h[16777216], g_xs_l[16777216];
static __device__ __nv_bfloat16 g_w1_h[67108864], g_w1_l[67108864];
static __device__ __nv_bfloat16 g_w2_h[67108864], g_w2_l[67108864];
static __device__ __nv_bfloat16 g_hid_h[67108864], g_hid_l[67108864];

__device__ __forceinline__ uint32_t smem_u32(const void* p) {
    uint32_t a;
    asm("{ .reg .u64 t; cvta.to.shared.u64 t, %1; cvt.u32.u64 %0, t; }"
        : "=r"(a) : "l"(p));
    return a;
}
#define SW128(x) ((x) ^ (((x) >> 3) & 0x70))

__device__ __forceinline__ uint32_t pack_bf2(float a, float b) {
    uint32_t r;
    asm("cvt.rn.bf16x2.f32 %0, %1, %2;" : "=r"(r) : "f"(b), "f"(a));
    return r;
}
__device__ __forceinline__ void ldsm4(uint32_t* r, uint32_t addr) {
    asm volatile("ldmatrix.sync.aligned.m8n8.x4.shared.b16 {%0,%1,%2,%3}, [%4];"
                 : "=r"(r[0]), "=r"(r[1]), "=r"(r[2]), "=r"(r[3]) : "r"(addr));
}
__device__ __forceinline__ void mma16816(float* c, const uint32_t* a,
                                         uint32_t b0, uint32_t b1) {
    asm volatile(
        "mma.sync.aligned.m16n8k16.row.col.f32.bf16.bf16.f32 "
        "{%0,%1,%2,%3}, {%4,%5,%6,%7}, {%8,%9}, {%0,%1,%2,%3};"
        : "+f"(c[0]), "+f"(c[1]), "+f"(c[2]), "+f"(c[3])
        : "r"(a[0]), "r"(a[1]), "r"(a[2]), "r"(a[3]), "r"(b0), "r"(b1));
}
__device__ __forceinline__ void cp16(uint32_t dst, const void* src) {
    asm volatile("cp.async.cg.shared.global [%0], [%1], 16;"
                 :: "r"(dst), "l"(src) : "memory");
}
#define CP_COMMIT() asm volatile("cp.async.commit_group;" ::: "memory")
#define CP_WAIT1()  asm volatile("cp.async.wait_group 1;" ::: "memory")

// -------- elementwise fp32 -> bf16 hi/lo planes --------
__global__ __launch_bounds__(256)
void split_f32_k(const float4* __restrict__ in, uint2* __restrict__ hi,
                 uint2* __restrict__ lo, int n4) {
    int i = blockIdx.x * 256 + threadIdx.x;
    if (i >= n4) return;
    float4 f = in[i];
    uint32_t h0 = pack_bf2(f.x, f.y), h1 = pack_bf2(f.z, f.w);
    float e0 = __uint_as_float(h0 << 16), e1 = __uint_as_float(h0 & 0xFFFF0000u);
    float e2 = __uint_as_float(h1 << 16), e3 = __uint_as_float(h1 & 0xFFFF0000u);
    hi[i] = make_uint2(h0, h1);
    lo[i] = make_uint2(pack_bf2(f.x - e0, f.y - e1), pack_bf2(f.z - e2, f.w - e3));
}

// SMEM stage (bf16, 64-elem rows = 128B, SW128 swizzled):
//   Ahi @0 (16KB)  Alo @16384  Bhi @32768 (32KB)  Blo @65536  -> 96KB/stage
static constexpr int A_LO = 16384, B_HI = 32768, B_LO = 65536;
static constexpr int STAGE = 98304;
static constexpr int SMEM_TOTAL = 2 * STAGE;  // 192 KB

template <int NCOLS, int KDIM, bool RELU, bool SPLIT>
__global__ __launch_bounds__(256, 1)
void ffn_mma7(const __nv_bfloat16* __restrict__ Ah, const __nv_bfloat16* __restrict__ Al,
              const __nv_bfloat16* __restrict__ Bh, const __nv_bfloat16* __restrict__ Bl,
              const float* __restrict__ bias,
              float* __restrict__ Cf,
              __nv_bfloat16* __restrict__ Ch, __nv_bfloat16* __restrict__ Cl)
{
    constexpr int NK = KDIM / 64;
    extern __shared__ char smem[];
    const uint32_t smb = smem_u32(smem);

    const int tid  = threadIdx.x;
    const int lane = tid & 31, warp = tid >> 5;
    const int wm = warp >> 2, wn = warp & 3;  // 2x4 grid, warp tile 64(M) x 64(N)
    const int e  = blockIdx.z;
    const int m0 = blockIdx.y * 128, n0 = blockIdx.x * 256;

    const __nv_bfloat16* Abh = Ah + ((size_t)e * 1024 + m0) * KDIM;
    const __nv_bfloat16* Abl = Al + ((size_t)e * 1024 + m0) * KDIM;
    const __nv_bfloat16* Bbh = Bh + ((size_t)e * NCOLS + n0) * KDIM;
    const __nv_bfloat16* Bbl = Bl + ((size_t)e * NCOLS + n0) * KDIM;

    // ldmatrix per-thread bases (R4-validated; A same, B extended to 64 cols)
    const int xmask = (lane & 7) << 4;
    const int a_b0 = (wm * 64 + (lane & 15)) * 128 + ((lane >> 4) & 1) * 16;
    const int b_b0 = (wn * 64 + (lane & 7) + ((lane >> 4) & 1) * 8) * 128 +
                     ((lane >> 3) & 1) * 16;

    float acc[4][8][4];
#pragma unroll
    for (int i = 0; i < 4; i++)
#pragma unroll
        for (int j = 0; j < 8; j++)
#pragma unroll
            for (int q = 0; q < 4; q++) acc[i][j][q] = 0.f;

    // staging (addresses recomputed each call to save registers):
    // A planes: 1024 16B-chunks (4/thread); B planes: 2048 (8/thread)
    auto stage = [&](int kt, uint32_t base) {
        const int kofs = kt * 64;
#pragma unroll
        for (int t = 0; t < 4; t++) {
            int s = tid + (t << 8);
            int row = s >> 3, c = s & 7;
            int sw = SW128(row * 128 + c * 16);
            size_t g = (size_t)row * KDIM + kofs + c * 8;
            cp16(base + sw,        Abh + g);
            cp16(base + A_LO + sw, Abl + g);
        }
#pragma unroll
        for (int t = 0; t < 8; t++) {
            int s = tid + (t << 8);
            int row = s >> 3, c = s & 7;
            int sw = SW128(row * 128 + c * 16);
            size_t g = (size_t)row * KDIM + kofs + c * 8;
            cp16(base + B_HI + sw, Bbh + g);
            cp16(base + B_LO + sw, Bbl + g);
        }
    };

    // ---- prologue: fill both stages ----
    stage(0, smb);         CP_COMMIT();
    stage(1, smb + STAGE); CP_COMMIT();
    CP_WAIT1();            // stage 0 resident
    __syncthreads();

    for (int kt = 0; kt < NK; ++kt) {
        const uint32_t sA = smb + (kt & 1) * STAGE;

#pragma unroll
        for (int k16 = 0; k16 < 4; k16++) {
            uint32_t ah[4][4], al[4][4], bh[4][4], bl[4][4];
#pragma unroll
            for (int mt = 0; mt < 4; mt++) {
                int off = (a_b0 + mt * 2048 + k16 * 32) ^ xmask;
                ldsm4(ah[mt], sA + off);
                ldsm4(al[mt], sA + A_LO + off);
            }
#pragma unroll
            for (int nt2 = 0; nt2 < 4; nt2++) {
                int off = (b_b0 + nt2 * 2048 + k16 * 32) ^ xmask;
                ldsm4(bh[nt2], sA + B_HI + off);
                ldsm4(bl[nt2], sA + B_LO + off);
            }
#pragma unroll
            for (int mt = 0; mt < 4; mt++)
#pragma unroll
                for (int nt = 0; nt < 8; nt++) {
                    const int g = nt >> 1, s2 = (nt & 1) * 2;
                    mma16816(acc[mt][nt], ah[mt], bh[g][s2], bh[g][s2 + 1]);
                    mma16816(acc[mt][nt], ah[mt], bl[g][s2], bl[g][s2 + 1]);
                    mma16816(acc[mt][nt], al[mt], bh[g][s2], bh[g][s2 + 1]);
                }
        }

        __syncthreads();                         // all warps done reading sA
        if (kt + 2 < NK) stage(kt + 2, sA);      // refill freed buffer
        CP_COMMIT();                             // uniform group accounting
        if (kt + 1 < NK) {
            CP_WAIT1();                          // stage kt+1 resident
            __syncthreads();
        }
    }

    // ---- epilogue ----
    const float* bp = bias + (size_t)e * NCOLS + n0 + wn * 64;
    float2 bvv[8];
#pragma unroll
    for (int nt = 0; nt < 8; nt++)
        bvv[nt] = *(const float2*)(bp + nt * 8 + (lane & 3) * 2);

    const size_t rbase = (size_t)e * 1024 + m0 + wm * 64;
#pragma unroll
    for (int mt = 0; mt < 4; mt++) {
        int r = mt * 16 + (lane >> 2);
#pragma unroll
        for (int nt = 0; nt < 8; nt++) {
            int col = n0 + wn * 64 + nt * 8 + (lane & 3) * 2;
            float2 v0, v1;
            v0.x = acc[mt][nt][0] + bvv[nt].x;
            v0.y = acc[mt][nt][1] + bvv[nt].y;
            v1.x = acc[mt][nt][2] + bvv[nt].x;
            v1.y = acc[mt][nt][3] + bvv[nt].y;
            if (RELU) {
                v0.x = fmaxf(v0.x, 0.f); v0.y = fmaxf(v0.y, 0.f);
                v1.x = fmaxf(v1.x, 0.f); v1.y = fmaxf(v1.y, 0.f);
            }
            const size_t i0 = (rbase + r) * NCOLS + col;
            const size_t i1 = (rbase + r + 8) * NCOLS + col;
            if (SPLIT) {
                uint32_t h0 = pack_bf2(v0.x, v0.y);
                float e0 = __uint_as_float(h0 << 16), e1 = __uint_as_float(h0 & 0xFFFF0000u);
                uint32_t l0 = pack_bf2(v0.x - e0, v0.y - e1);
                uint32_t h1 = pack_bf2(v1.x, v1.y);
                float e2 = __uint_as_float(h1 << 16), e3 = __uint_as_float(h1 & 0xFFFF0000u);
                uint32_t l1 = pack_bf2(v1.x - e2, v1.y - e3);
                *(uint32_t*)(Ch + i0) = h0;
                *(uint32_t*)(Cl + i0) = l0;
                *(uint32_t*)(Ch + i1) = h1;
                *(uint32_t*)(Cl + i1) = l1;
            } else {
                *(float2*)(Cf + i0) = v0;
                *(float2*)(Cf + i1) = v1;
            }
        }
    }
}

extern "C" void kernel_launch(void* const* d_in, const int* in_sizes, int n_in,
                              void* d_out, int out_size) {
    (void)in_sizes; (void)n_in; (void)out_size;
    const float* xs = (const float*)d_in[0];
    const float* w1 = (const float*)d_in[2];
    const float* b1 = (const float*)d_in[3];
    const float* w2 = (const float*)d_in[4];
    const float* b2 = (const float*)d_in[5];
    float* out = (float*)d_out;

    void *xh, *xl, *w1h, *w1l, *w2h, *w2l, *hh, *hl;
    cudaGetSymbolAddress(&xh,  g_xs_h);  cudaGetSymbolAddress(&xl,  g_xs_l);
    cudaGetSymbolAddress(&w1h, g_w1_h);  cudaGetSymbolAddress(&w1l, g_w1_l);
    cudaGetSymbolAddress(&w2h, g_w2_h);  cudaGetSymbolAddress(&w2l, g_w2_l);
    cudaGetSymbolAddress(&hh,  g_hid_h); cudaGetSymbolAddress(&hl,  g_hid_l);

    cudaFuncSetAttribute(ffn_mma7<4096, 1024, true, true>,
                         cudaFuncAttributeMaxDynamicSharedMemorySize, SMEM_TOTAL);
    cudaFuncSetAttribute(ffn_mma7<1024, 4096, false, false>,
                         cudaFuncAttributeMaxDynamicSharedMemorySize, SMEM_TOTAL);

    // Pre-split operands to bf16 hi/lo planes
    split_f32_k<<<16384, 256>>>((const float4*)xs, (uint2*)xh, (uint2*)xl, 16777216 / 4);
    split_f32_k<<<65536, 256>>>((const float4*)w1, (uint2*)w1h, (uint2*)w1l, 67108864 / 4);
    split_f32_k<<<65536, 256>>>((const float4*)w2, (uint2*)w2h, (uint2*)w2l, 67108864 / 4);

    // GEMM1: bias+relu, split-output hidden planes (N=4096 -> 16 n-blocks)
    ffn_mma7<4096, 1024, true, true><<<dim3(16, 8, 16), 256, SMEM_TOTAL>>>(
        (const __nv_bfloat16*)xh, (const __nv_bfloat16*)xl,
        (const __nv_bfloat16*)w1h, (const __nv_bfloat16*)w1l,
        b1, nullptr, (__nv_bfloat16*)hh, (__nv_bfloat16*)hl);
    // GEMM2: bias, fp32 out (N=1024 -> 4 n-blocks)
    ffn_mma7<1024, 4096, false, false><<<dim3(4, 8, 16), 256, SMEM_TOTAL>>>(
        (const __nv_bfloat16*)hh, (const __nv_bfloat16*)hl,
        (const __nv_bfloat16*)w2h, (const __nv_bfloat16*)w2l,
        b2, out, nullptr, nullptr);
}

// round 10
// speedup vs baseline: 1.0427x; 1.0420x over previous
#include <cuda_runtime.h>
#include <cuda_bf16.h>
#include <cstdint>
#include <cstddef>

// E=16, D=1024, H=4096, N=16384 (1024 tokens/expert, contiguous).
// GEMM1: per-expert [1024 x 4096 x 1024], relu(X*W1^T + b1) -> hidden (bf16 hi/lo)
// GEMM2: per-expert [1024 x 1024 x 4096], H*W2^T + b2       -> fp32 out
// bf16 hi/lo 3-pass (Ootomo) mma.sync m16n8k16.
// R10 = R4 geometry exactly (BM=128,BN=128,256thr, 3x64KB cp.async ring),
// but MMAs emitted PASS-MAJOR: all 16 hh, then 16 hl, then 16 lh. asm volatile
// preserves program order, so this stretches per-accumulator RAW distance from
// 1 to 16 instructions and removes the 2x HMMA-latency stall per acc group
// that capped tensor at ~74% in R4/R7/R8/R9.

static __device__ __nv_bfloat16 g_xs_h[16777216], g_xs_l[16777216];
static __device__ __nv_bfloat16 g_w1_h[67108864], g_w1_l[67108864];
static __device__ __nv_bfloat16 g_w2_h[67108864], g_w2_l[67108864];
static __device__ __nv_bfloat16 g_hid_h[67108864], g_hid_l[67108864];

__device__ __forceinline__ uint32_t smem_u32(const void* p) {
    uint32_t a;
    asm("{ .reg .u64 t; cvta.to.shared.u64 t, %1; cvt.u32.u64 %0, t; }"
        : "=r"(a) : "l"(p));
    return a;
}
#define SW128(x) ((x) ^ (((x) >> 3) & 0x70))

__device__ __forceinline__ uint32_t pack_bf2(float a, float b) {
    uint32_t r;
    asm("cvt.rn.bf16x2.f32 %0, %1, %2;" : "=r"(r) : "f"(b), "f"(a));
    return r;
}
__device__ __forceinline__ void ldsm4(uint32_t* r, uint32_t addr) {
    asm volatile("ldmatrix.sync.aligned.m8n8.x4.shared.b16 {%0,%1,%2,%3}, [%4];"
                 : "=r"(r[0]), "=r"(r[1]), "=r"(r[2]), "=r"(r[3]) : "r"(addr));
}
__device__ __forceinline__ void mma16816(float* c, const uint32_t* a,
                                         uint32_t b0, uint32_t b1) {
    asm volatile(
        "mma.sync.aligned.m16n8k16.row.col.f32.bf16.bf16.f32 "
        "{%0,%1,%2,%3}, {%4,%5,%6,%7}, {%8,%9}, {%0,%1,%2,%3};"
        : "+f"(c[0]), "+f"(c[1]), "+f"(c[2]), "+f"(c[3])
        : "r"(a[0]), "r"(a[1]), "r"(a[2]), "r"(a[3]), "r"(b0), "r"(b1));
}
__device__ __forceinline__ void cp16(uint32_t dst, const void* src) {
    asm volatile("cp.async.cg.shared.global [%0], [%1], 16;"
                 :: "r"(dst), "l"(src) : "memory");
}
#define CP_COMMIT() asm volatile("cp.async.commit_group;" ::: "memory")
#define CP_WAIT1()  asm volatile("cp.async.wait_group 1;" ::: "memory")

// -------- elementwise fp32 -> bf16 hi/lo planes --------
__global__ __launch_bounds__(256)
void split_f32_k(const float4* __restrict__ in, uint2* __restrict__ hi,
                 uint2* __restrict__ lo, int n4) {
    int i = blockIdx.x * 256 + threadIdx.x;
    if (i >= n4) return;
    float4 f = in[i];
    uint32_t h0 = pack_bf2(f.x, f.y), h1 = pack_bf2(f.z, f.w);
    float e0 = __uint_as_float(h0 << 16), e1 = __uint_as_float(h0 & 0xFFFF0000u);
    float e2 = __uint_as_float(h1 << 16), e3 = __uint_as_float(h1 & 0xFFFF0000u);
    hi[i] = make_uint2(h0, h1);
    lo[i] = make_uint2(pack_bf2(f.x - e0, f.y - e1), pack_bf2(f.z - e2, f.w - e3));
}

// SMEM stage (bf16, 64-elem rows = 128B, SW128):
//   Ahi @0 (16KB)  Alo @16384  Bhi @32768  Blo @49152  -> 64KB/stage, 3 stages
static constexpr int STAGE = 65536;
static constexpr int SMEM_TOTAL = 3 * STAGE;  // 192 KB

template <int NCOLS, int KDIM, bool RELU, bool SPLIT>
__global__ __launch_bounds__(256, 1)
void ffn_mma8(const __nv_bfloat16* __restrict__ Ah, const __nv_bfloat16* __restrict__ Al,
              const __nv_bfloat16* __restrict__ Bh, const __nv_bfloat16* __restrict__ Bl,
              const float* __restrict__ bias,
              float* __restrict__ Cf,
              __nv_bfloat16* __restrict__ Ch, __nv_bfloat16* __restrict__ Cl)
{
    constexpr int NK = KDIM / 64;
    extern __shared__ char smem[];
    const uint32_t smb = smem_u32(smem);

    const int tid  = threadIdx.x;
    const int lane = tid & 31, warp = tid >> 5;
    const int wm = warp >> 2, wn = warp & 3;  // 2x4, warp tile 64(M) x 32(N)
    const int e  = blockIdx.z;
    const int m0 = blockIdx.y * 128, n0 = blockIdx.x * 128;

    const __nv_bfloat16* Abh = Ah + ((size_t)e * 1024 + m0) * KDIM;
    const __nv_bfloat16* Abl = Al + ((size_t)e * 1024 + m0) * KDIM;
    const __nv_bfloat16* Bbh = Bh + ((size_t)e * NCOLS + n0) * KDIM;
    const __nv_bfloat16* Bbl = Bl + ((size_t)e * NCOLS + n0) * KDIM;

    // staging: chunk s = tid + t*256; row = s>>3 (0..127), c = s&7
    int sws[4];
    size_t goff[4];
#pragma unroll
    for (int t = 0; t < 4; t++) {
        int s = tid + (t << 8);
        int row = s >> 3, c = s & 7;
        sws[t]  = SW128(row * 128 + c * 16);
        goff[t] = (size_t)row * KDIM + c * 8;
    }

    // ldmatrix per-thread bases (validated R3/R4)
    const int xmask = (lane & 7) << 4;
    const int a_b0 = (wm * 64 + (lane & 15)) * 128 + ((lane >> 4) & 1) * 16;
    const int b_b0 = (wn * 32 + (lane & 7) + ((lane >> 4) & 1) * 8) * 128 +
                     ((lane >> 3) & 1) * 16;

    float acc[4][4][4];
#pragma unroll
    for (int i = 0; i < 4; i++)
#pragma unroll
        for (int j = 0; j < 4; j++)
#pragma unroll
            for (int q = 0; q < 4; q++) acc[i][j][q] = 0.f;

    auto stage = [&](int kt, uint32_t base) {
        const int kofs = kt * 64;
#pragma unroll
        for (int t = 0; t < 4; t++) {
            const size_t g = goff[t] + kofs;
            cp16(base + sws[t],          Abh + g);
            cp16(base + 16384 + sws[t],  Abl + g);
            cp16(base + 32768 + sws[t],  Bbh + g);
            cp16(base + 49152 + sws[t],  Bbl + g);
        }
    };

    // ---- prologue: fill stages 0,1 ----
    stage(0, smb);         CP_COMMIT();
    stage(1, smb + STAGE); CP_COMMIT();
    CP_WAIT1();            // stage 0 resident
    __syncthreads();

    for (int kt = 0; kt < NK; ++kt) {
        const uint32_t sA = smb + (kt % 3) * STAGE;

        if (kt + 2 < NK) stage(kt + 2, smb + ((kt + 2) % 3) * STAGE);
        CP_COMMIT();  // one group per iter (may be empty at tail)

#pragma unroll
        for (int k16 = 0; k16 < 4; k16++) {
            uint32_t ah[4][4], al[4][4], bh[2][4], bl[2][4];
#pragma unroll
            for (int mt = 0; mt < 4; mt++) {
                int off = (a_b0 + mt * 2048 + k16 * 32) ^ xmask;
                ldsm4(ah[mt], sA + off);
                ldsm4(al[mt], sA + 16384 + off);
            }
#pragma unroll
            for (int nt2 = 0; nt2 < 2; nt2++) {
                int off = (b_b0 + nt2 * 2048 + k16 * 32) ^ xmask;
                ldsm4(bh[nt2], sA + 32768 + off);
                ldsm4(bl[nt2], sA + 49152 + off);
            }
            // PASS-MAJOR: per-acc RAW distance = 16 instructions, not 1.
#pragma unroll
            for (int mt = 0; mt < 4; mt++)
#pragma unroll
                for (int nt = 0; nt < 4; nt++) {
                    const int g = nt >> 1, s2 = (nt & 1) * 2;
                    mma16816(acc[mt][nt], ah[mt], bh[g][s2], bh[g][s2 + 1]);
                }
#pragma unroll
            for (int mt = 0; mt < 4; mt++)
#pragma unroll
                for (int nt = 0; nt < 4; nt++) {
                    const int g = nt >> 1, s2 = (nt & 1) * 2;
                    mma16816(acc[mt][nt], ah[mt], bl[g][s2], bl[g][s2 + 1]);
                }
#pragma unroll
            for (int mt = 0; mt < 4; mt++)
#pragma unroll
                for (int nt = 0; nt < 4; nt++) {
                    const int g = nt >> 1, s2 = (nt & 1) * 2;
                    mma16816(acc[mt][nt], al[mt], bh[g][s2], bh[g][s2 + 1]);
                }
        }

        if (kt + 1 < NK) {
            CP_WAIT1();        // stage kt+1 resident (kt+2 in flight)
            __syncthreads();   // frees ring slot kt%3
        }
    }

    // ---- epilogue ----
    const float* bp = bias + (size_t)e * NCOLS + n0 + wn * 32;
    float2 bvv[4];
#pragma unroll
    for (int nt = 0; nt < 4; nt++)
        bvv[nt] = *(const float2*)(bp + nt * 8 + (lane & 3) * 2);

    const size_t rbase = (size_t)e * 1024 + m0 + wm * 64;
#pragma unroll
    for (int mt = 0; mt < 4; mt++) {
        int r = mt * 16 + (lane >> 2);
#pragma unroll
        for (int nt = 0; nt < 4; nt++) {
            int col = n0 + wn * 32 + nt * 8 + (lane & 3) * 2;
            float2 v0, v1;
            v0.x = acc[mt][nt][0] + bvv[nt].x;
            v0.y = acc[mt][nt][1] + bvv[nt].y;
            v1.x = acc[mt][nt][2] + bvv[nt].x;
            v1.y = acc[mt][nt][3] + bvv[nt].y;
            if (RELU) {
                v0.x = fmaxf(v0.x, 0.f); v0.y = fmaxf(v0.y, 0.f);
                v1.x = fmaxf(v1.x, 0.f); v1.y = fmaxf(v1.y, 0.f);
            }
            const size_t i0 = (rbase + r) * NCOLS + col;
            const size_t i1 = (rbase + r + 8) * NCOLS + col;
            if (SPLIT) {
                uint32_t h0 = pack_bf2(v0.x, v0.y);
                float e0 = __uint_as_float(h0 << 16), e1 = __uint_as_float(h0 & 0xFFFF0000u);
                uint32_t l0 = pack_bf2(v0.x - e0, v0.y - e1);
                uint32_t h1 = pack_bf2(v1.x, v1.y);
                float e2 = __uint_as_float(h1 << 16), e3 = __uint_as_float(h1 & 0xFFFF0000u);
                uint32_t l1 = pack_bf2(v1.x - e2, v1.y - e3);
                *(uint32_t*)(Ch + i0) = h0;
                *(uint32_t*)(Cl + i0) = l0;
                *(uint32_t*)(Ch + i1) = h1;
                *(uint32_t*)(Cl + i1) = l1;
            } else {
                *(float2*)(Cf + i0) = v0;
                *(float2*)(Cf + i1) = v1;
            }
        }
    }
}

extern "C" void kernel_launch(void* const* d_in, const int* in_sizes, int n_in,
                              void* d_out, int out_size) {
    (void)in_sizes; (void)n_in; (void)out_size;
    const float* xs = (const float*)d_in[0];
    const float* w1 = (const float*)d_in[2];
    const float* b1 = (const float*)d_in[3];
    const float* w2 = (const float*)d_in[4];
    const float* b2 = (const float*)d_in[5];
    float* out = (float*)d_out;

    void *xh, *xl, *w1h, *w1l, *w2h, *w2l, *hh, *hl;
    cudaGetSymbolAddress(&xh,  g_xs_h);  cudaGetSymbolAddress(&xl,  g_xs_l);
    cudaGetSymbolAddress(&w1h, g_w1_h);  cudaGetSymbolAddress(&w1l, g_w1_l);
    cudaGetSymbolAddress(&w2h, g_w2_h);  cudaGetSymbolAddress(&w2l, g_w2_l);
    cudaGetSymbolAddress(&hh,  g_hid_h); cudaGetSymbolAddress(&hl,  g_hid_l);

    cudaFuncSetAttribute(ffn_mma8<4096, 1024, true, true>,
                         cudaFuncAttributeMaxDynamicSharedMemorySize, SMEM_TOTAL);
    cudaFuncSetAttribute(ffn_mma8<1024, 4096, false, false>,
                         cudaFuncAttributeMaxDynamicSharedMemorySize, SMEM_TOTAL);

    // Pre-split operands to bf16 hi/lo planes
    split_f32_k<<<16384, 256>>>((const float4*)xs, (uint2*)xh, (uint2*)xl, 16777216 / 4);
    split_f32_k<<<65536, 256>>>((const float4*)w1, (uint2*)w1h, (uint2*)w1l, 67108864 / 4);
    split_f32_k<<<65536, 256>>>((const float4*)w2, (uint2*)w2h, (uint2*)w2l, 67108864 / 4);

    // GEMM1: bias+relu, split-output hidden planes
    ffn_mma8<4096, 1024, true, true><<<dim3(32, 8, 16), 256, SMEM_TOTAL>>>(
        (const __nv_bfloat16*)xh, (const __nv_bfloat16*)xl,
        (const __nv_bfloat16*)w1h, (const __nv_bfloat16*)w1l,
        b1, nullptr, (__nv_bfloat16*)hh, (__nv_bfloat16*)hl);
    // GEMM2: bias, fp32 out
    ffn_mma8<1024, 4096, false, false><<<dim3(8, 8, 16), 256, SMEM_TOTAL>>>(
        (const __nv_bfloat16*)hh, (const __nv_bfloat16*)hl,
        (const __nv_bfloat16*)w2h, (const __nv_bfloat16*)w2l,
        b2, out, nullptr, nullptr);
}